// round 7
// baseline (speedup 1.0000x reference)
#include <cuda_runtime.h>
#include <cstdint>
#include <math.h>

#define CLASS_PERIOD 360
#define VEC_PER_ROW  (CLASS_PERIOD / 4)    // 90 float4 per window
#define ROWS_PER_BLOCK 8
#define BLOCK_THREADS 128                  // 4 warps, 2 rows per warp
#define WIN_BYTES (CLASS_PERIOD * 4)       // 1440 B, multiple of 16
#define TOTAL_TX  (ROWS_PER_BLOCK * 2 * WIN_BYTES)   // 23040 B
#define MAX_BLOCKS 4096

// Scratch (no device allocation allowed): per-block partials + ticket counter.
__device__ float        g_block_partials[MAX_BLOCKS];
__device__ unsigned int g_ticket = 0;

__device__ __forceinline__ uint32_t smem_u32(const void* p) {
    uint32_t a;
    asm("{ .reg .u64 t; cvta.to.shared.u64 t, %1; cvt.u32.u64 %0, t; }"
        : "=r"(a) : "l"(p));
    return a;
}

__device__ __forceinline__ void bulk_copy_g2s(uint32_t dst, const void* src,
                                              uint32_t bytes, uint32_t mbar) {
    asm volatile(
        "cp.async.bulk.shared::cta.global.mbarrier::complete_tx::bytes "
        "[%0], [%1], %2, [%3];"
        :: "r"(dst), "l"(src), "r"(bytes), "r"(mbar) : "memory");
}

// ---------------------------------------------------------------------------
__global__ __launch_bounds__(BLOCK_THREADS)
void vp_fused_kernel(const float* __restrict__ preds,
                     const float* __restrict__ labels,
                     const int*   __restrict__ obj_classes,  // int32
                     float* __restrict__ out,
                     int W, int B)
{
    __shared__ __align__(16) float s_p[ROWS_PER_BLOCK][CLASS_PERIOD];
    __shared__ __align__(16) float s_l[ROWS_PER_BLOCK][CLASS_PERIOD];
    __shared__ __align__(8)  unsigned long long s_mbar;
    __shared__ float s_row[ROWS_PER_BLOCK];
    __shared__ bool  s_is_last;

    const int tid    = threadIdx.x;
    const int lane   = tid & 31;
    const int warp   = tid >> 5;
    const int lane16 = lane & 15;
    const int half   = lane >> 4;
    const int nblocks = gridDim.x;
    const int row0   = blockIdx.x * ROWS_PER_BLOCK;

    const uint32_t mbar = smem_u32(&s_mbar);

    if (tid == 0) {
        asm volatile("mbarrier.init.shared.b64 [%0], %1;"
                     :: "r"(mbar), "r"(1) : "memory");
        asm volatile("fence.proxy.async.shared::cta;" ::: "memory");
    }
    __syncthreads();

    // Thread 0: arrive+expect_tx, then issue all 16 bulk copies in order.
    if (tid == 0) {
        asm volatile("mbarrier.arrive.expect_tx.shared.b64 _, [%0], %1;"
                     :: "r"(mbar), "r"((uint32_t)TOTAL_TX) : "memory");
        #pragma unroll
        for (int r = 0; r < ROWS_PER_BLOCK; r++) {
            const long long base = (long long)(row0 + r) * (long long)W
                                 + (long long)obj_classes[row0 + r] * CLASS_PERIOD;
            bulk_copy_g2s(smem_u32(&s_p[r][0]), preds  + base, WIN_BYTES, mbar);
            bulk_copy_g2s(smem_u32(&s_l[r][0]), labels + base, WIN_BYTES, mbar);
        }
    }

    // Wait for all 23040 bytes (acquire orders the smem reads below).
    {
        uint32_t done;
        asm volatile(
            "{\n\t.reg .pred p;\n\t"
            "mbarrier.try_wait.parity.acquire.cta.shared::cta.b64 p, [%1], %2;\n\t"
            "selp.b32 %0, 1, 0, p;\n\t}"
            : "=r"(done) : "r"(mbar), "r"(0u) : "memory");
        if (!done) {
            asm volatile(
                "{\n\t.reg .pred P1;\n\t"
                "WL_%=:\n\t"
                "mbarrier.try_wait.parity.acquire.cta.shared::cta.b64 P1, [%0], %1, 0x989680;\n\t"
                "@P1 bra.uni WD_%=;\n\t"
                "bra.uni WL_%=;\n\t"
                "WD_%=:\n\t}"
                :: "r"(mbar), "r"(0u) : "memory");
        }
    }

    // ---------------- compute: 2 rows per warp, half-warp each ------------
    const int r = warp * 2 + half;
    const float4* __restrict__ p4 = (const float4*)&s_p[r][0];
    const float4* __restrict__ l4 = (const float4*)&s_l[r][0];

    const bool a5 = (lane16 + 80) < VEC_PER_ROW;   // lane16 < 10

    float4 pv0 = p4[lane16];
    float4 pv1 = p4[lane16 + 16];
    float4 pv2 = p4[lane16 + 32];
    float4 pv3 = p4[lane16 + 48];
    float4 pv4 = p4[lane16 + 64];
    float4 lv0 = l4[lane16];
    float4 lv1 = l4[lane16 + 16];
    float4 lv2 = l4[lane16 + 32];
    float4 lv3 = l4[lane16 + 48];
    float4 lv4 = l4[lane16 + 64];
    float4 pv5 = make_float4(0.f, 0.f, 0.f, 0.f);
    float4 lv5 = make_float4(0.f, 0.f, 0.f, 0.f);
    if (a5) { pv5 = p4[lane16 + 80]; lv5 = l4[lane16 + 80]; }

    float es = __expf(pv0.x) + __expf(pv0.y) + __expf(pv0.z) + __expf(pv0.w)
             + __expf(pv1.x) + __expf(pv1.y) + __expf(pv1.z) + __expf(pv1.w)
             + __expf(pv2.x) + __expf(pv2.y) + __expf(pv2.z) + __expf(pv2.w)
             + __expf(pv3.x) + __expf(pv3.y) + __expf(pv3.z) + __expf(pv3.w)
             + __expf(pv4.x) + __expf(pv4.y) + __expf(pv4.z) + __expf(pv4.w);
    float dt = lv0.x*pv0.x + lv0.y*pv0.y + lv0.z*pv0.z + lv0.w*pv0.w
             + lv1.x*pv1.x + lv1.y*pv1.y + lv1.z*pv1.z + lv1.w*pv1.w
             + lv2.x*pv2.x + lv2.y*pv2.y + lv2.z*pv2.z + lv2.w*pv2.w
             + lv3.x*pv3.x + lv3.y*pv3.y + lv3.z*pv3.z + lv3.w*pv3.w
             + lv4.x*pv4.x + lv4.y*pv4.y + lv4.z*pv4.z + lv4.w*pv4.w;
    float ls = lv0.x + lv0.y + lv0.z + lv0.w
             + lv1.x + lv1.y + lv1.z + lv1.w
             + lv2.x + lv2.y + lv2.z + lv2.w
             + lv3.x + lv3.y + lv3.z + lv3.w
             + lv4.x + lv4.y + lv4.z + lv4.w;
    if (a5) {
        es += __expf(pv5.x) + __expf(pv5.y) + __expf(pv5.z) + __expf(pv5.w);
        dt += lv5.x*pv5.x + lv5.y*pv5.y + lv5.z*pv5.z + lv5.w*pv5.w;
        ls += lv5.x + lv5.y + lv5.z + lv5.w;
    }

    // Half-warp reduction (xor 8,4,2,1 stays within each 16-lane half).
    #pragma unroll
    for (int off = 8; off > 0; off >>= 1) {
        es += __shfl_xor_sync(0xFFFFFFFFu, es, off);
        dt += __shfl_xor_sync(0xFFFFFFFFu, dt, off);
        ls += __shfl_xor_sync(0xFFFFFFFFu, ls, off);
    }

    if (lane16 == 0)
        s_row[r] = dt - __logf(es) * ls;   // sum_j l_j*log_softmax(p)_j
    __syncthreads();

    if (tid == 0) {
        float bp = 0.0f;
        #pragma unroll
        for (int w = 0; w < ROWS_PER_BLOCK; w++) bp += s_row[w];
        g_block_partials[blockIdx.x] = bp;
        __threadfence();
        unsigned int t = atomicAdd(&g_ticket, 1u);
        s_is_last = (t == (unsigned)(nblocks - 1));
    }
    __syncthreads();

    // ---------------- last block: final reduce ----------------------------
    if (s_is_last) {
        float acc = 0.0f;
        for (int i = tid; i < nblocks; i += BLOCK_THREADS)
            acc += g_block_partials[i];

        #pragma unroll
        for (int off = 16; off > 0; off >>= 1)
            acc += __shfl_xor_sync(0xFFFFFFFFu, acc, off);

        __shared__ float s_fin[BLOCK_THREADS / 32];
        if (lane == 0) s_fin[warp] = acc;
        __syncthreads();
        if (tid == 0) {
            float tot = 0.0f;
            #pragma unroll
            for (int w = 0; w < BLOCK_THREADS / 32; w++) tot += s_fin[w];
            out[0] = -tot / ((float)CLASS_PERIOD * (float)B);
            g_ticket = 0;   // reset for next replay (all increments complete)
        }
    }
}

// ---------------------------------------------------------------------------
extern "C" void kernel_launch(void* const* d_in, const int* in_sizes, int n_in,
                              void* d_out, int out_size)
{
    const float* preds  = (const float*)d_in[0];
    const float* labels = (const float*)d_in[1];
    const int*   objcls = (const int*)d_in[2];

    const int B = in_sizes[2];                // 16384
    const int W = in_sizes[0] / B;            // 4320
    const int nblocks = B / ROWS_PER_BLOCK;   // 2048

    vp_fused_kernel<<<nblocks, BLOCK_THREADS>>>(preds, labels, objcls,
                                                (float*)d_out, W, B);
}